// round 11
// baseline (speedup 1.0000x reference)
#include <cuda_runtime.h>

#define NN    50000
#define DIN   128
#define DOUT  64
#define EE    800000
#define GTILE 64          // nodes per GEMM block
#define HTS   66          // sHT row stride in floats (8B-aligned, conflict-light)
#define NB1   49          // scan1 blocks (49*1024 >= NN)

typedef unsigned long long u64;

// ---------------------------------------------------------------------------
// Device scratch
// ---------------------------------------------------------------------------
__device__ float  g_X[NN * DOUT];     // projected features
__device__ int    g_cnt[NN];          // degree counters -> scatter cursors
__device__ int    g_rowptr[NN + 1];   // CSR row offsets
__device__ int    g_scan[NN];         // block-local exclusive scan
__device__ int    g_bsum[NB1];        // per-block totals
__device__ float2 g_edge[EE];         // CSR (col as int bits, val)

// ---------------------------------------------------------------------------
// Packed fp32x2 FMA (sm_10x, PTX-only)
// ---------------------------------------------------------------------------
__device__ __forceinline__ u64 ffma2(u64 a, u64 b, u64 c) {
    u64 d;
    asm("fma.rn.f32x2 %0, %1, %2, %3;" : "=l"(d) : "l"(a), "l"(b), "l"(c));
    return d;
}
__device__ __forceinline__ u64 pack2(float lo, float hi) {
    u64 r;
    asm("mov.b64 %0, {%1, %2};" : "=l"(r) : "f"(lo), "f"(hi));
    return r;
}
__device__ __forceinline__ void unpack2(u64 v, float& lo, float& hi) {
    asm("mov.b64 {%0, %1}, %2;" : "=f"(lo), "=f"(hi) : "l"(v));
}

// ---------------------------------------------------------------------------
// CSR build (R4-proven versions)
// ---------------------------------------------------------------------------
__global__ void zero_cnt_kernel() {
    int i = blockIdx.x * blockDim.x + threadIdx.x;
    if (i < NN) g_cnt[i] = 0;
}

__global__ void hist_kernel(const int* __restrict__ rows) {
    int e = blockIdx.x * blockDim.x + threadIdx.x;
    if (e < EE) atomicAdd(&g_cnt[rows[e]], 1);
}

// scan1: per-block exclusive scan of 1024 degrees + block total
__global__ __launch_bounds__(1024) void scan1_kernel() {
    __shared__ int wsum[32];
    int tid  = threadIdx.x;
    int i    = blockIdx.x * 1024 + tid;
    int lane = tid & 31, warp = tid >> 5;

    int orig = (i < NN) ? g_cnt[i] : 0;
    int v = orig;
    #pragma unroll
    for (int o = 1; o < 32; o <<= 1) {
        int n = __shfl_up_sync(0xffffffffu, v, o);
        if (lane >= o) v += n;
    }
    if (lane == 31) wsum[warp] = v;
    __syncthreads();
    if (warp == 0) {
        int s = wsum[lane];
        #pragma unroll
        for (int o = 1; o < 32; o <<= 1) {
            int n = __shfl_up_sync(0xffffffffu, s, o);
            if (lane >= o) s += n;
        }
        wsum[lane] = s;
    }
    __syncthreads();
    int base = (warp > 0) ? wsum[warp - 1] : 0;
    if (i < NN) g_scan[i] = base + v - orig;
    if (tid == 1023) g_bsum[blockIdx.x] = wsum[31];
}

// scan3: redundant warp-scan of the 49 block totals, then finalize rowptr
// and seed scatter cursors (scan2 folded in — measured win in R7).
__global__ __launch_bounds__(256) void scan3_kernel() {
    __shared__ int sOff[NB1];
    int tid = threadIdx.x;

    if (tid < 32) {
        int a = (2 * tid     < NB1) ? g_bsum[2 * tid]     : 0;
        int b = (2 * tid + 1 < NB1) ? g_bsum[2 * tid + 1] : 0;
        int s = a + b;
        int incl = s;
        #pragma unroll
        for (int o = 1; o < 32; o <<= 1) {
            int n = __shfl_up_sync(0xffffffffu, incl, o);
            if (tid >= o) incl += n;
        }
        int excl = incl - s;
        if (2 * tid     < NB1) sOff[2 * tid]     = excl;
        if (2 * tid + 1 < NB1) sOff[2 * tid + 1] = excl + a;
    }
    __syncthreads();

    int i = blockIdx.x * 256 + tid;
    if (i < NN) {
        int r = g_scan[i] + sOff[i >> 10];
        g_rowptr[i] = r;
        g_cnt[i]    = r;
    }
    if (i == 0) g_rowptr[NN] = EE;
}

// scatter: one edge per thread, one packed 8B store (R4-proven)
__global__ void scatter_kernel(const int* __restrict__ rows,
                               const int* __restrict__ cols,
                               const float* __restrict__ vals) {
    int e = blockIdx.x * blockDim.x + threadIdx.x;
    if (e < EE) {
        int pos = atomicAdd(&g_cnt[rows[e]], 1);
        g_edge[pos] = make_float2(__int_as_float(cols[e]), vals[e]);
    }
}

// ---------------------------------------------------------------------------
// Fused L2-normalize + BN(eval) + Linear(128->64)+bias -> g_X
//   k-major node tile (sHT) + pre-duplicated W (sWd2) so every FFMA2 operand
//   comes straight out of shared memory already packed. 128 threads,
//   thread = 4 node-pairs x 4 cols -> 16 fma.rn.f32x2 per k.
// ---------------------------------------------------------------------------
__global__ __launch_bounds__(128) void fused_gemm_kernel(
    const float* __restrict__ H,
    const float* __restrict__ gamma,
    const float* __restrict__ beta,
    const float* __restrict__ mean,
    const float* __restrict__ var,
    const float* __restrict__ W,
    const float* __restrict__ bias)
{
    __shared__ float2 sWd2[DIN * DOUT];       // 64 KB, W duplicated per lane-pair
    __shared__ float  sHT[DIN * HTS];         // 33.8 KB, k-major: sHT[k*HTS + n]
    __shared__ float  sInv[GTILE];

    const int tid    = threadIdx.x;
    const int node0  = blockIdx.x * GTILE;
    const int nvalid = min(GTILE, NN - node0);

    // BN per-feature constants, one feature per thread (DIN == blockDim)
    const float bnA = gamma[tid] * rsqrtf(var[tid] + 1e-5f);
    const float bnC = beta[tid] - mean[tid] * bnA;

    // Stage W duplicated: sWd2[k*64+j] = (W[k][j], W[k][j])
    #pragma unroll
    for (int i = tid; i < DIN * DOUT; i += 128) {
        float w = W[i];
        sWd2[i] = make_float2(w, w);
    }

    // Stage H tile transposed into sHT (coalesced float4 read along k)
    #pragma unroll
    for (int i4 = tid; i4 < GTILE * (DIN / 4); i4 += 128) {
        int r = i4 >> 5;           // node in tile
        int c = (i4 & 31) * 4;     // k
        float4 v = (r < nvalid)
            ? reinterpret_cast<const float4*>(H)[(node0 + r) * (DIN / 4) + (c >> 2)]
            : make_float4(1.f, 0.f, 0.f, 0.f);
        sHT[(c + 0) * HTS + r] = v.x;
        sHT[(c + 1) * HTS + r] = v.y;
        sHT[(c + 2) * HTS + r] = v.z;
        sHT[(c + 3) * HTS + r] = v.w;
    }
    __syncthreads();

    // Row L2 norms from sHT: 2 threads per node, 64 k's each
    {
        int r = tid >> 1, l = tid & 1;
        float ss = 0.f;
        #pragma unroll 8
        for (int i = 0; i < 64; i++) {
            float v = sHT[(l * 64 + i) * HTS + r];
            ss = fmaf(v, v, ss);
        }
        ss += __shfl_xor_sync(0xffffffffu, ss, 1);
        if (l == 0) sInv[r] = 1.0f / fmaxf(sqrtf(ss), 1e-12f);
    }
    __syncthreads();

    // Apply normalize + BN in place: thread owns feature k = tid
    {
        float* rowp = &sHT[tid * HTS];
        #pragma unroll 8
        for (int n = 0; n < GTILE; n++)
            rowp[n] = fmaf(rowp[n] * sInv[n], bnA, bnC);
    }
    __syncthreads();

    // GEMM: thread = (4 node pairs, 4 cols); all operands pre-packed in smem
    const int jg = tid & 15;          // 16 col groups * 4 = 64 cols
    const int ng = tid >> 4;          // 8 node groups * 8 = 64 nodes
    const int n0 = ng * 8;
    const int j0 = jg * 4;

    u64 acc[4][4];
    #pragma unroll
    for (int p = 0; p < 4; p++)
        #pragma unroll
        for (int j = 0; j < 4; j++) acc[p][j] = 0ull;

    #pragma unroll 4
    for (int k = 0; k < DIN; k++) {
        // 4 packed node pairs: LDS.64 each, naturally aligned
        const u64* hrow = reinterpret_cast<const u64*>(&sHT[k * HTS + n0]);
        u64 h0 = hrow[0];
        u64 h1 = hrow[1];
        u64 h2 = hrow[2];
        u64 h3 = hrow[3];
        // 4 duplicated col weights: two LDS.128
        const ulonglong2* wrow =
            reinterpret_cast<const ulonglong2*>(&sWd2[k * DOUT + j0]);
        ulonglong2 wa = wrow[0];   // cols j0, j0+1
        ulonglong2 wb = wrow[1];   // cols j0+2, j0+3

        acc[0][0] = ffma2(h0, wa.x, acc[0][0]);
        acc[0][1] = ffma2(h0, wa.y, acc[0][1]);
        acc[0][2] = ffma2(h0, wb.x, acc[0][2]);
        acc[0][3] = ffma2(h0, wb.y, acc[0][3]);
        acc[1][0] = ffma2(h1, wa.x, acc[1][0]);
        acc[1][1] = ffma2(h1, wa.y, acc[1][1]);
        acc[1][2] = ffma2(h1, wb.x, acc[1][2]);
        acc[1][3] = ffma2(h1, wb.y, acc[1][3]);
        acc[2][0] = ffma2(h2, wa.x, acc[2][0]);
        acc[2][1] = ffma2(h2, wa.y, acc[2][1]);
        acc[2][2] = ffma2(h2, wb.x, acc[2][2]);
        acc[2][3] = ffma2(h2, wb.y, acc[2][3]);
        acc[3][0] = ffma2(h3, wa.x, acc[3][0]);
        acc[3][1] = ffma2(h3, wa.y, acc[3][1]);
        acc[3][2] = ffma2(h3, wb.x, acc[3][2]);
        acc[3][3] = ffma2(h3, wb.y, acc[3][3]);
    }

    float4 bb = *reinterpret_cast<const float4*>(&bias[j0]);
    #pragma unroll
    for (int p = 0; p < 4; p++) {
        float4 lo, hi;
        unpack2(acc[p][0], lo.x, hi.x);
        unpack2(acc[p][1], lo.y, hi.y);
        unpack2(acc[p][2], lo.z, hi.z);
        unpack2(acc[p][3], lo.w, hi.w);
        lo.x += bb.x; lo.y += bb.y; lo.z += bb.z; lo.w += bb.w;
        hi.x += bb.x; hi.y += bb.y; hi.z += bb.z; hi.w += bb.w;
        int na = n0 + 2 * p, nb = na + 1;
        if (na < nvalid)
            *reinterpret_cast<float4*>(&g_X[(node0 + na) * DOUT + j0]) = lo;
        if (nb < nvalid)
            *reinterpret_cast<float4*>(&g_X[(node0 + nb) * DOUT + j0]) = hi;
    }
}

// ---------------------------------------------------------------------------
// Row-parallel SpMM + LeakyReLU: 16 threads per row, float4 per lane
// (R4-proven form).
// ---------------------------------------------------------------------------
__global__ __launch_bounds__(256) void spmm_leaky_kernel(float* __restrict__ out)
{
    int gid  = blockIdx.x * 256 + threadIdx.x;
    int row  = gid >> 4;
    if (row >= NN) return;
    int lane = gid & 15;
    int c0   = lane * 4;

    int s = g_rowptr[row];
    int e = g_rowptr[row + 1];

    float4 a = make_float4(0.f, 0.f, 0.f, 0.f);

    for (int p = s; p < e; ++p) {
        float2 ev = g_edge[p];
        int   col = __float_as_int(ev.x);
        float v   = ev.y;
        float4 x  = *reinterpret_cast<const float4*>(&g_X[col * DOUT + c0]);
        a.x = fmaf(v, x.x, a.x);
        a.y = fmaf(v, x.y, a.y);
        a.z = fmaf(v, x.z, a.z);
        a.w = fmaf(v, x.w, a.w);
    }

    a.x = a.x >= 0.f ? a.x : 0.01f * a.x;
    a.y = a.y >= 0.f ? a.y : 0.01f * a.y;
    a.z = a.z >= 0.f ? a.z : 0.01f * a.z;
    a.w = a.w >= 0.f ? a.w : 0.01f * a.w;

    *reinterpret_cast<float4*>(&out[row * DOUT + c0]) = a;
}

// ---------------------------------------------------------------------------
extern "C" void kernel_launch(void* const* d_in, const int* in_sizes, int n_in,
                              void* d_out, int out_size) {
    const float* H     = (const float*)d_in[0];
    const int*   rows  = (const int*)  d_in[1];
    const int*   cols  = (const int*)  d_in[2];
    const float* vals  = (const float*)d_in[3];
    const float* gamma = (const float*)d_in[4];
    const float* beta  = (const float*)d_in[5];
    const float* rmean = (const float*)d_in[6];
    const float* rvar  = (const float*)d_in[7];
    const float* W     = (const float*)d_in[8];
    const float* b     = (const float*)d_in[9];
    float* out = (float*)d_out;

    // CSR build
    zero_cnt_kernel<<<(NN + 255) / 256, 256>>>();
    hist_kernel<<<(EE + 255) / 256, 256>>>(rows);
    scan1_kernel<<<NB1, 1024>>>();
    scan3_kernel<<<(NN + 255) / 256, 256>>>();
    scatter_kernel<<<(EE + 255) / 256, 256>>>(rows, cols, vals);

    // Dense part
    fused_gemm_kernel<<<(NN + GTILE - 1) / GTILE, 128>>>(H, gamma, beta,
                                                         rmean, rvar, W, b);

    // Sparse aggregation + activation
    spmm_leaky_kernel<<<(NN * 16 + 255) / 256, 256>>>(out);
}

// round 12
// speedup vs baseline: 1.2560x; 1.2560x over previous
#include <cuda_runtime.h>

#define NN    50000
#define DIN   128
#define DOUT  64
#define EE    800000
#define GTILE 64          // nodes per GEMM block
#define SHPAD 132         // padded sH row stride (breaks bank conflicts)
#define NB1   49          // scan1 blocks (49*1024 >= NN)

// ---------------------------------------------------------------------------
// Device scratch
// ---------------------------------------------------------------------------
__device__ float  g_X[NN * DOUT];     // projected features
__device__ int    g_cnt[NN];          // degree counters -> scatter cursors
__device__ int    g_rowptr[NN + 1];   // CSR row offsets
__device__ int    g_scan[NN];         // block-local exclusive scan
__device__ int    g_bsum[NB1];        // per-block totals
__device__ float2 g_edge[EE];         // CSR (col as int bits, val)

// ---------------------------------------------------------------------------
// CSR build (R4/R5-proven forms)
// ---------------------------------------------------------------------------
__global__ void zero_cnt_kernel() {
    int i = blockIdx.x * blockDim.x + threadIdx.x;
    if (i < NN) g_cnt[i] = 0;
}

__global__ void hist_kernel(const int* __restrict__ rows) {
    int e = blockIdx.x * blockDim.x + threadIdx.x;
    if (e < EE) atomicAdd(&g_cnt[rows[e]], 1);
}

// scan1: per-block exclusive scan of 1024 degrees + block total
__global__ __launch_bounds__(1024) void scan1_kernel() {
    __shared__ int wsum[32];
    int tid  = threadIdx.x;
    int i    = blockIdx.x * 1024 + tid;
    int lane = tid & 31, warp = tid >> 5;

    int orig = (i < NN) ? g_cnt[i] : 0;
    int v = orig;
    #pragma unroll
    for (int o = 1; o < 32; o <<= 1) {
        int n = __shfl_up_sync(0xffffffffu, v, o);
        if (lane >= o) v += n;
    }
    if (lane == 31) wsum[warp] = v;
    __syncthreads();
    if (warp == 0) {
        int s = wsum[lane];
        #pragma unroll
        for (int o = 1; o < 32; o <<= 1) {
            int n = __shfl_up_sync(0xffffffffu, s, o);
            if (lane >= o) s += n;
        }
        wsum[lane] = s;
    }
    __syncthreads();
    int base = (warp > 0) ? wsum[warp - 1] : 0;
    if (i < NN) g_scan[i] = base + v - orig;
    if (tid == 1023) g_bsum[blockIdx.x] = wsum[31];
}

// scan3: redundant warp-scan of the 49 block totals in every block, then
// finalize rowptr and seed scatter cursors (scan2 folded in; proven in R7).
__global__ __launch_bounds__(256) void scan3_kernel() {
    __shared__ int sOff[NB1];
    int tid = threadIdx.x;

    if (tid < 32) {
        int a = (2 * tid     < NB1) ? g_bsum[2 * tid]     : 0;
        int b = (2 * tid + 1 < NB1) ? g_bsum[2 * tid + 1] : 0;
        int s = a + b;
        int incl = s;
        #pragma unroll
        for (int o = 1; o < 32; o <<= 1) {
            int n = __shfl_up_sync(0xffffffffu, incl, o);
            if (tid >= o) incl += n;
        }
        int excl = incl - s;
        if (2 * tid     < NB1) sOff[2 * tid]     = excl;
        if (2 * tid + 1 < NB1) sOff[2 * tid + 1] = excl + a;
    }
    __syncthreads();

    int i = blockIdx.x * 256 + tid;
    if (i < NN) {
        int r = g_scan[i] + sOff[i >> 10];
        g_rowptr[i] = r;
        g_cnt[i]    = r;
    }
    if (i == 0) g_rowptr[NN] = EE;
}

// scatter: one edge per thread, one packed 8B store
__global__ void scatter_kernel(const int* __restrict__ rows,
                               const int* __restrict__ cols,
                               const float* __restrict__ vals) {
    int e = blockIdx.x * blockDim.x + threadIdx.x;
    if (e < EE) {
        int pos = atomicAdd(&g_cnt[rows[e]], 1);
        g_edge[pos] = make_float2(__int_as_float(cols[e]), vals[e]);
    }
}

// ---------------------------------------------------------------------------
// Fused L2-normalize + BN(eval) + Linear(128->64)+bias -> g_X
//   R5-proven scalar version: 64 nodes / block, 128 threads,
//   each thread 8 nodes x 4 cols. smem ~66 KB -> 3 CTAs/SM.
// ---------------------------------------------------------------------------
__global__ __launch_bounds__(128) void fused_gemm_kernel(
    const float* __restrict__ H,
    const float* __restrict__ gamma,
    const float* __restrict__ beta,
    const float* __restrict__ mean,
    const float* __restrict__ var,
    const float* __restrict__ W,
    const float* __restrict__ bias)
{
    __shared__ float sW[DIN * DOUT];        // 32 KB
    __shared__ float sH[GTILE * SHPAD];     // 33.8 KB
    __shared__ float sA[DIN];
    __shared__ float sC[DIN];
    __shared__ float sInv[GTILE];

    const int tid    = threadIdx.x;
    const int node0  = blockIdx.x * GTILE;
    const int nvalid = min(GTILE, NN - node0);

    // Stage W (float4, coalesced)
    #pragma unroll
    for (int i = tid; i < DIN * DOUT / 4; i += 128)
        reinterpret_cast<float4*>(sW)[i] =
            reinterpret_cast<const float4*>(W)[i];

    // BN per-feature constants
    {
        float a = gamma[tid] * rsqrtf(var[tid] + 1e-5f);
        sA[tid] = a;
        sC[tid] = beta[tid] - mean[tid] * a;
    }

    // Stage H tile
    #pragma unroll
    for (int i4 = tid; i4 < GTILE * (DIN / 4); i4 += 128) {
        int r = i4 >> 5;
        int c = (i4 & 31) * 4;
        float4 v = (r < nvalid)
            ? reinterpret_cast<const float4*>(H)[(node0 + r) * (DIN / 4) + (c >> 2)]
            : make_float4(1.f, 0.f, 0.f, 0.f);
        *reinterpret_cast<float4*>(&sH[r * SHPAD + c]) = v;
    }
    __syncthreads();

    // Row L2 norms: 2 threads per row, 64 elems each
    {
        int r = tid >> 1, l = tid & 1;
        float ss = 0.f;
        #pragma unroll
        for (int i = 0; i < 16; i++) {
            float4 v = *reinterpret_cast<float4*>(&sH[r * SHPAD + l * 64 + i * 4]);
            ss += v.x * v.x + v.y * v.y + v.z * v.z + v.w * v.w;
        }
        ss += __shfl_xor_sync(0xffffffffu, ss, 1);
        if (l == 0) sInv[r] = 1.0f / fmaxf(sqrtf(ss), 1e-12f);
    }
    __syncthreads();

    // normalize + BN in place
    #pragma unroll
    for (int i4 = tid; i4 < GTILE * (DIN / 4); i4 += 128) {
        int r = i4 >> 5;
        int c = (i4 & 31) * 4;
        float inv = sInv[r];
        float4 h  = *reinterpret_cast<float4*>(&sH[r * SHPAD + c]);
        float4 a  = *reinterpret_cast<float4*>(&sA[c]);
        float4 cc = *reinterpret_cast<float4*>(&sC[c]);
        h.x = fmaf(h.x * inv, a.x, cc.x);
        h.y = fmaf(h.y * inv, a.y, cc.y);
        h.z = fmaf(h.z * inv, a.z, cc.z);
        h.w = fmaf(h.w * inv, a.w, cc.w);
        *reinterpret_cast<float4*>(&sH[r * SHPAD + c]) = h;
    }
    __syncthreads();

    // GEMM: thread = (8 nodes, 4 cols)
    const int jg = tid & 15;
    const int ng = tid >> 4;
    const int n0 = ng * 8;
    const int j0 = jg * 4;

    float4 acc[8];
    #pragma unroll
    for (int i = 0; i < 8; i++) acc[i] = make_float4(0.f, 0.f, 0.f, 0.f);

    #pragma unroll 4
    for (int k = 0; k < DIN; k++) {
        float4 w = *reinterpret_cast<float4*>(&sW[k * DOUT + j0]);
        #pragma unroll
        for (int i = 0; i < 8; i++) {
            float h = sH[(n0 + i) * SHPAD + k];
            acc[i].x = fmaf(h, w.x, acc[i].x);
            acc[i].y = fmaf(h, w.y, acc[i].y);
            acc[i].z = fmaf(h, w.z, acc[i].z);
            acc[i].w = fmaf(h, w.w, acc[i].w);
        }
    }

    float4 bb = *reinterpret_cast<const float4*>(&bias[j0]);
    #pragma unroll
    for (int i = 0; i < 8; i++) {
        if (n0 + i < nvalid) {
            float4 a = acc[i];
            a.x += bb.x; a.y += bb.y; a.z += bb.z; a.w += bb.w;
            *reinterpret_cast<float4*>(&g_X[(node0 + n0 + i) * DOUT + j0]) = a;
        }
    }
}

// ---------------------------------------------------------------------------
// Row-parallel SpMM + LeakyReLU: 16 threads per row, float4 per lane
// ---------------------------------------------------------------------------
__global__ __launch_bounds__(256) void spmm_leaky_kernel(float* __restrict__ out)
{
    int gid  = blockIdx.x * 256 + threadIdx.x;
    int row  = gid >> 4;
    if (row >= NN) return;
    int lane = gid & 15;
    int c0   = lane * 4;

    int s = g_rowptr[row];
    int e = g_rowptr[row + 1];

    float4 a = make_float4(0.f, 0.f, 0.f, 0.f);

    for (int p = s; p < e; ++p) {
        float2 ev = g_edge[p];
        int   col = __float_as_int(ev.x);
        float v   = ev.y;
        float4 x  = *reinterpret_cast<const float4*>(&g_X[col * DOUT + c0]);
        a.x = fmaf(v, x.x, a.x);
        a.y = fmaf(v, x.y, a.y);
        a.z = fmaf(v, x.z, a.z);
        a.w = fmaf(v, x.w, a.w);
    }

    a.x = a.x >= 0.f ? a.x : 0.01f * a.x;
    a.y = a.y >= 0.f ? a.y : 0.01f * a.y;
    a.z = a.z >= 0.f ? a.z : 0.01f * a.z;
    a.w = a.w >= 0.f ? a.w : 0.01f * a.w;

    *reinterpret_cast<float4*>(&out[row * DOUT + c0]) = a;
}

// ---------------------------------------------------------------------------
// Launch: fork the (independent) GEMM onto a second stream so it overlaps
// the CSR-build chain; join with an event before the SpMM.
// Host-side stream/event create/destroy happens only at capture time —
// the timed graph replay contains just the two parallel kernel chains.
// ---------------------------------------------------------------------------
extern "C" void kernel_launch(void* const* d_in, const int* in_sizes, int n_in,
                              void* d_out, int out_size) {
    const float* H     = (const float*)d_in[0];
    const int*   rows  = (const int*)  d_in[1];
    const int*   cols  = (const int*)  d_in[2];
    const float* vals  = (const float*)d_in[3];
    const float* gamma = (const float*)d_in[4];
    const float* beta  = (const float*)d_in[5];
    const float* rmean = (const float*)d_in[6];
    const float* rvar  = (const float*)d_in[7];
    const float* W     = (const float*)d_in[8];
    const float* b     = (const float*)d_in[9];
    float* out = (float*)d_out;

    cudaStream_t s0 = 0;            // the (captured) default stream
    cudaStream_t s1;
    cudaEvent_t  evFork, evJoin;
    cudaStreamCreateWithFlags(&s1, cudaStreamNonBlocking);
    cudaEventCreateWithFlags(&evFork, cudaEventDisableTiming);
    cudaEventCreateWithFlags(&evJoin, cudaEventDisableTiming);

    // Fork: GEMM chain on s1, independent of CSR build
    cudaEventRecord(evFork, s0);
    cudaStreamWaitEvent(s1, evFork, 0);
    fused_gemm_kernel<<<(NN + GTILE - 1) / GTILE, 128, 0, s1>>>(
        H, gamma, beta, rmean, rvar, W, b);
    cudaEventRecord(evJoin, s1);

    // CSR build chain on s0 (runs concurrently with the GEMM)
    zero_cnt_kernel<<<(NN + 255) / 256, 256, 0, s0>>>();
    hist_kernel<<<(EE + 255) / 256, 256, 0, s0>>>(rows);
    scan1_kernel<<<NB1, 1024, 0, s0>>>();
    scan3_kernel<<<(NN + 255) / 256, 256, 0, s0>>>();
    scatter_kernel<<<(EE + 255) / 256, 256, 0, s0>>>(rows, cols, vals);

    // Join: SpMM needs both g_X (s1) and the CSR arrays (s0)
    cudaStreamWaitEvent(s0, evJoin, 0);
    spmm_leaky_kernel<<<(NN * 16 + 255) / 256, 256, 0, s0>>>(out);

    // Deferred destruction; safe during capture and eager runs
    cudaEventDestroy(evFork);
    cudaEventDestroy(evJoin);
    cudaStreamDestroy(s1);
}